// round 11
// baseline (speedup 1.0000x reference)
#include <cuda_runtime.h>
#include <cuda_fp16.h>
#include <math.h>
#include <stdint.h>

constexpr int NB = 16, C = 512, L = 384, H = 8, D = 64, ME = 384;

__device__ __half g_x0T[NB * L * C];
__device__ __half g_x1T[NB * L * C];
__device__ __half g_wqh[C * C], g_wkh[C * C], g_wvh[C * C], g_wdh[C * C];
__device__ __half g_qh[NB * C * L], g_kh[NB * C * L], g_vh[NB * C * L];
__device__ __half g_attT[NB * L * C];
__device__ float g_gate[NB * H * L];

// ---------------------------------------------------------------------------
// helpers
// ---------------------------------------------------------------------------
__device__ __forceinline__ uint32_t h2pack(float lo, float hi) {
    uint32_t u;
    asm("cvt.rn.f16x2.f32 %0, %1, %2;" : "=r"(u) : "f"(hi), "f"(lo));
    return u;
}

__device__ __forceinline__ void mma16(float* c, const uint32_t* a, const uint32_t* b) {
    asm("mma.sync.aligned.m16n8k16.row.col.f32.f16.f16.f32 "
        "{%0,%1,%2,%3}, {%4,%5,%6,%7}, {%8,%9}, {%0,%1,%2,%3};"
        : "+f"(c[0]), "+f"(c[1]), "+f"(c[2]), "+f"(c[3])
        : "r"(a[0]), "r"(a[1]), "r"(a[2]), "r"(a[3]), "r"(b[0]), "r"(b[1]));
}

__device__ __forceinline__ uint32_t smaddr(const void* p) {
    return (uint32_t)__cvta_generic_to_shared(p);
}
__device__ __forceinline__ void ldsm4(uint32_t* r, uint32_t a) {
    asm volatile("ldmatrix.sync.aligned.m8n8.x4.shared.b16 {%0,%1,%2,%3}, [%4];"
                 : "=r"(r[0]), "=r"(r[1]), "=r"(r[2]), "=r"(r[3]) : "r"(a));
}
__device__ __forceinline__ void ldsm4t(uint32_t* r, uint32_t a) {
    asm volatile("ldmatrix.sync.aligned.m8n8.x4.trans.shared.b16 {%0,%1,%2,%3}, [%4];"
                 : "=r"(r[0]), "=r"(r[1]), "=r"(r[2]), "=r"(r[3]) : "r"(a));
}
__device__ __forceinline__ void cpa16(uint32_t dst, const void* src) {
    asm volatile("cp.async.cg.shared.global [%0], [%1], 16;" :: "r"(dst), "l"(src));
}
__device__ __forceinline__ void cpa_commit() { asm volatile("cp.async.commit_group;"); }
__device__ __forceinline__ void cpa_wait0() {
    asm volatile("cp.async.wait_group 0;" ::: "memory");
}
__device__ __forceinline__ void cpa_wait1() {
    asm volatile("cp.async.wait_group 1;" ::: "memory");
}

// ---------------------------------------------------------------------------
// 1) Fused preprocess + transpose: x0T/x1T[n][l][c] (half), vectorized writes
// ---------------------------------------------------------------------------
__global__ void __launch_bounds__(256) prep_t(const float* __restrict__ x,
                                              const float* __restrict__ xorg,
                                              const float* __restrict__ abspos,
                                              const float* __restrict__ qkpos,
                                              const float* __restrict__ qkorg,
                                              const float* __restrict__ vorg) {
    __shared__ float t0[32][33], t1[32][33];
    int n = blockIdx.z, ct = blockIdx.y, lt = blockIdx.x;
    int tx = threadIdx.x, ty = threadIdx.y;
#pragma unroll
    for (int s = 0; s < 4; s++) {
        int c = ct * 32 + ty + 8 * s;
        int l = lt * 32 + tx;
        size_t idx = ((size_t)n * C + c) * L + l;
        int gg = c >> 3;
        float xv = x[idx], xo = xorg[idx], ap = abspos[idx];
        t0[ty + 8 * s][tx] = xv + xo * vorg[gg];
        t1[ty + 8 * s][tx] = xv + xo * qkorg[gg] + ap * qkpos[gg];
    }
    __syncthreads();
    int c16 = tx & 15, lh = tx >> 4;
    int c = ct * 32 + c16 * 2;
#pragma unroll
    for (int s = 0; s < 2; s++) {
        int lidx = ty * 2 + lh + 16 * s;
        int l = lt * 32 + lidx;
        size_t o = ((size_t)n * L + l) * C + c;
        *(uint32_t*)(g_x0T + o) = h2pack(t0[c16 * 2][lidx], t0[c16 * 2 + 1][lidx]);
        *(uint32_t*)(g_x1T + o) = h2pack(t1[c16 * 2][lidx], t1[c16 * 2 + 1][lidx]);
    }
}

// 1b) round weights to half
__global__ void round_w_h(const float* __restrict__ q, const float* __restrict__ k,
                          const float* __restrict__ v, const float* __restrict__ d) {
    int i = blockIdx.x * blockDim.x + threadIdx.x;
    int mat = i >> 15;
    int j = (i & 32767) * 8;
    const float* s = mat == 0 ? q : mat == 1 ? k : mat == 2 ? v : d;
    __half* dst = mat == 0 ? g_wqh : mat == 1 ? g_wkh : mat == 2 ? g_wvh : g_wdh;
    float4 f0 = *(const float4*)(s + j);
    float4 f1 = *(const float4*)(s + j + 4);
    uint4 o;
    o.x = h2pack(f0.x, f0.y); o.y = h2pack(f0.z, f0.w);
    o.z = h2pack(f1.x, f1.y); o.w = h2pack(f1.z, f1.w);
    *(uint4*)(dst + j) = o;
}

// ---------------------------------------------------------------------------
// f16 GEMM core, 3-stage cp.async pipeline. Out[m][l] = sum_k A[m][k] B[l][k]
//   Dynamic smem: A stages [3][128][40], B stages [3][128][40]  (61440 B)
// ---------------------------------------------------------------------------
constexpr int GH_STAGE = 128 * 40;               // halves per stage per operand
constexpr int GH_B = 3 * GH_STAGE * 2 * 2;       // 61440 bytes

template <bool TOHALF>
__device__ __forceinline__ void gemm_h(const __half* __restrict__ A,
                                       const __half* __restrict__ Bx,
                                       void* Obv, const float* __restrict__ bias,
                                       int m0, int n0) {
    extern __shared__ __half dsm[];
    __half* Asb = dsm;
    __half* Bsb = dsm + 3 * GH_STAGE;
    int t = threadIdx.x;
    int ar = t >> 1, ac = (t & 1) * 16;
    const __half* Ap = A + (size_t)(m0 + ar) * C + ac;
    const __half* Bp = Bx + (size_t)(n0 + ar) * C + ac;
    int w = t >> 5, lane = t & 31;
    int wm = (w >> 1) * 32, wn = (w & 1) * 64;
    int g = lane >> 2, tg2 = (lane & 3) * 2;

    float acc[2][8][4] = {};
    uint32_t arow_off = (uint32_t)(ar * 40 + ac);

    // prologue: issue slabs 0 and 1
#pragma unroll
    for (int s = 0; s < 2; s++) {
        uint32_t ad = smaddr(Asb + s * GH_STAGE) + arow_off * 2;
        uint32_t bd = smaddr(Bsb + s * GH_STAGE) + arow_off * 2;
        cpa16(ad, Ap + s * 32); cpa16(ad + 16, Ap + s * 32 + 8);
        cpa16(bd, Bp + s * 32); cpa16(bd + 16, Bp + s * 32 + 8);
        cpa_commit();
    }

    int a_row = (lane & 15), a_col = (lane >> 4) * 8;
    int b_row = ((lane >> 4) & 1) * 8 + (lane & 7), b_col = ((lane >> 3) & 1) * 8;

    int buf = 0;
    for (int k0 = 0; k0 < C; k0 += 32) {
        cpa_wait1();               // slab for 'buf' resident (next may be in flight)
        __syncthreads();
        if (k0 + 64 < C) {
            int nb = buf + 2; if (nb >= 3) nb -= 3;
            uint32_t ad = smaddr(Asb + nb * GH_STAGE) + arow_off * 2;
            uint32_t bd = smaddr(Bsb + nb * GH_STAGE) + arow_off * 2;
            cpa16(ad, Ap + k0 + 64); cpa16(ad + 16, Ap + k0 + 72);
            cpa16(bd, Bp + k0 + 64); cpa16(bd + 16, Bp + k0 + 72);
            cpa_commit();
        }
        const __half* Ab = Asb + buf * GH_STAGE;
        const __half* Bb = Bsb + buf * GH_STAGE;
#pragma unroll
        for (int ks = 0; ks < 32; ks += 16) {
            uint32_t af[2][4], bf[8][2];
#pragma unroll
            for (int mt = 0; mt < 2; mt++)
                ldsm4(af[mt], smaddr(Ab + (wm + mt * 16 + a_row) * 40 + ks + a_col));
#pragma unroll
            for (int ntp = 0; ntp < 4; ntp++) {
                uint32_t rr[4];
                ldsm4(rr, smaddr(Bb + (wn + ntp * 16 + b_row) * 40 + ks + b_col));
                bf[2 * ntp][0] = rr[0]; bf[2 * ntp][1] = rr[1];
                bf[2 * ntp + 1][0] = rr[2]; bf[2 * ntp + 1][1] = rr[3];
            }
#pragma unroll
            for (int mt = 0; mt < 2; mt++)
#pragma unroll
                for (int nt = 0; nt < 8; nt++)
                    mma16(acc[mt][nt], af[mt], bf[nt]);
        }
        buf++; if (buf >= 3) buf = 0;
    }
#pragma unroll
    for (int mt = 0; mt < 2; mt++) {
        int mrow = m0 + wm + mt * 16 + g;
        if (TOHALF) {
            __half* Ob = (__half*)Obv;
#pragma unroll
            for (int nt = 0; nt < 8; nt++) {
                int col = n0 + wn + nt * 8 + tg2;
                *(uint32_t*)(Ob + (size_t)mrow * L + col) = h2pack(acc[mt][nt][0], acc[mt][nt][1]);
                *(uint32_t*)(Ob + (size_t)(mrow + 8) * L + col) = h2pack(acc[mt][nt][2], acc[mt][nt][3]);
            }
        } else {
            float* Ob = (float*)Obv;
            float bv0 = bias[mrow], bv1 = bias[mrow + 8];
#pragma unroll
            for (int nt = 0; nt < 8; nt++) {
                int col = n0 + wn + nt * 8 + tg2;
                *(float2*)(Ob + (size_t)mrow * L + col) =
                    make_float2(acc[mt][nt][0] + bv0, acc[mt][nt][1] + bv0);
                *(float2*)(Ob + (size_t)(mrow + 8) * L + col) =
                    make_float2(acc[mt][nt][2] + bv1, acc[mt][nt][3] + bv1);
            }
        }
    }
}

__global__ void __launch_bounds__(256, 2) qkv_h() {
    int z = blockIdx.z;
    int b = z / 3, which = z - 3 * b;
    const __half* A = which == 0 ? g_wqh : which == 1 ? g_wkh : g_wvh;
    const __half* Bx = (which == 2 ? g_x0T : g_x1T) + (size_t)b * L * C;
    __half* Ob = (which == 0 ? g_qh : which == 1 ? g_kh : g_vh) + (size_t)b * C * L;
    gemm_h<true>(A, Bx, Ob, nullptr, blockIdx.x * 128, blockIdx.y * 128);
}

__global__ void __launch_bounds__(256, 2) dense_h(float* __restrict__ Out,
                                                  const float* __restrict__ bias) {
    int b = blockIdx.z;
    gemm_h<false>(g_wdh, g_attT + (size_t)b * L * C, Out + (size_t)b * C * L,
                  bias, blockIdx.x * 128, blockIdx.y * 128);
}

// ---------------------------------------------------------------------------
// 3) Gate (f32, exact)
// ---------------------------------------------------------------------------
__global__ void __launch_bounds__(128) gate_kernel(const float* __restrict__ x,
                                                   const float* __restrict__ gate_w,
                                                   const float* __restrict__ gate_b) {
    __shared__ float ws[H * C];
    int n = blockIdx.y;
    int l = blockIdx.x * 128 + threadIdx.x;
    int t = threadIdx.x;
#pragma unroll
    for (int i = 0; i < H * C / (128 * 4); i++)
        *(float4*)&ws[(i * 128 + t) * 4] = *(const float4*)&gate_w[(i * 128 + t) * 4];
    __syncthreads();

    const float* xb = x + (size_t)n * C * L + l;
    float acc[H];
#pragma unroll
    for (int h = 0; h < H; h++) acc[h] = gate_b[h];
    for (int c = 0; c < C; c++) {
        float xv = xb[(size_t)c * L];
#pragma unroll
        for (int h = 0; h < H; h++)
            acc[h] = fmaf(ws[h * C + c], xv, acc[h]);
    }
#pragma unroll
    for (int h = 0; h < H; h++)
        g_gate[((size_t)n * H + h) * L + l] = acc[h];
}

// ---------------------------------------------------------------------------
// 4) Fused flash attention
// ---------------------------------------------------------------------------
constexpr int FQS = 0;          // [64][136] half
constexpr int FKS = 17408;
constexpr int FVS = 34816;
constexpr int FPS = 52224;      // [128][136]
constexpr int FREL = 87040;
constexpr int FGM = 88064;
constexpr int FBM = 88576;
constexpr int FBS = 89600;
constexpr int FA_B = 90624;

__global__ void __launch_bounds__(256) flash_h(const float* __restrict__ relpos,
                                               const float* __restrict__ mask,
                                               const float* __restrict__ norm) {
    extern __shared__ char sm[];
    __half* Qs = (__half*)(sm + FQS);
    __half* Ks = (__half*)(sm + FKS);
    __half* Vs = (__half*)(sm + FVS);
    __half* Ps = (__half*)(sm + FPS);
    float* rel_s = (float*)(sm + FREL);
    float* gm_s = (float*)(sm + FGM);
    float* bufM = (float*)(sm + FBM);
    float* bufS = (float*)(sm + FBS);

    int i0 = blockIdx.x * 128;
    int z = blockIdx.y;
    int n = z / H, h = z - n * H;
    const __half* Qb = g_qh + ((size_t)n * C + h * D) * L;
    const __half* Kb = g_kh + ((size_t)n * C + h * D) * L;
    const __half* Vb = g_vh + ((size_t)n * C + h * D) * L;
    float inv = 1.0f / norm[n];

    int t = threadIdx.x, w = t >> 5, lane = t & 31;
    int wm = (w >> 1) * 32, wn = (w & 1) * 64, wd = (w & 1) * 32;
    int g = lane >> 2, tg2 = (lane & 3) * 2;

    int at_row = ((lane >> 4) & 1) * 8 + (lane & 7), at_col = ((lane >> 3) & 1) * 8;
    int bt_row = ((lane >> 3) & 1) * 8 + (lane & 7), bt_col = ((lane >> 4) & 1) * 8;
    int a_row = (lane & 15), a_col = (lane >> 4) * 8;
    int b_row = ((lane >> 4) & 1) * 8 + (lane & 7), b_col = ((lane >> 3) & 1) * 8;

    {
        int dd = t >> 2, cc = (t & 3) * 32;
        uint32_t dq = smaddr(Qs + dd * 136 + cc);
        const __half* s = Qb + (size_t)dd * L + i0 + cc;
        cpa16(dq, s); cpa16(dq + 16, s + 8);
        cpa16(dq + 32, s + 16); cpa16(dq + 48, s + 24);
        cpa_commit();
    }

    float Oacc[2][4][4] = {};
    float m_pr[2][2] = {{-1e30f, -1e30f}, {-1e30f, -1e30f}};
    float l_run[2][2] = {{0.f, 0.f}, {0.f, 0.f}};

    for (int jt = 0; jt < 3; jt++) {
        int j0 = jt * 128;
        {
            int dd = t >> 2, cc = (t & 3) * 32;
            uint32_t dk = smaddr(Ks + dd * 136 + cc);
            const __half* s = Kb + (size_t)dd * L + j0 + cc;
            cpa16(dk, s); cpa16(dk + 16, s + 8);
            cpa16(dk + 32, s + 16); cpa16(dk + 48, s + 24);
            uint32_t dv = smaddr(Vs + dd * 136 + cc);
            const __half* sv = Vb + (size_t)dd * L + j0 + cc;
            cpa16(dv, sv); cpa16(dv + 16, sv + 8);
            cpa16(dv + 32, sv + 16); cpa16(dv + 48, sv + 24);
            cpa_commit();
        }
        if (t < 128)
            gm_s[t] = g_gate[(size_t)z * L + j0 + t] + mask[(size_t)n * L + j0 + t];
        rel_s[t] = relpos[min(257 + j0 - i0 + t, 2 * ME - 2)];
        cpa_wait0();
        __syncthreads();

        // ---- QK MMA ----
        float acc[2][8][4] = {};
#pragma unroll
        for (int ks = 0; ks < 64; ks += 16) {
            uint32_t af[2][4], bf[8][2];
#pragma unroll
            for (int mt = 0; mt < 2; mt++)
                ldsm4t(af[mt], smaddr(&Qs[(ks + at_row) * 136 + wm + mt * 16 + at_col]));
#pragma unroll
            for (int ntp = 0; ntp < 4; ntp++) {
                uint32_t rr[4];
                ldsm4t(rr, smaddr(&Ks[(ks + bt_row) * 136 + wn + ntp * 16 + bt_col]));
                bf[2 * ntp][0] = rr[0]; bf[2 * ntp][1] = rr[1];
                bf[2 * ntp + 1][0] = rr[2]; bf[2 * ntp + 1][1] = rr[3];
            }
#pragma unroll
            for (int mt = 0; mt < 2; mt++)
#pragma unroll
                for (int nt = 0; nt < 8; nt++)
                    mma16(acc[mt][nt], af[mt], bf[nt]);
        }

        // ---- bias + per-slot max ----
        float rmax[2][2];
#pragma unroll
        for (int mt = 0; mt < 2; mt++) {
            rmax[mt][0] = -1e30f; rmax[mt][1] = -1e30f;
            int rbase = wm + mt * 16 + g;
            int idx0 = 127 - rbase;
#pragma unroll
            for (int nt = 0; nt < 8; nt++) {
                int c0 = wn + nt * 8 + tg2;
                float gm0 = gm_s[c0], gm1 = gm_s[c0 + 1];
                float s00 = (acc[mt][nt][0] + rel_s[idx0 + c0] + gm0) * inv;
                float s01 = (acc[mt][nt][1] + rel_s[idx0 + c0 + 1] + gm1) * inv;
                float s10 = (acc[mt][nt][2] + rel_s[idx0 - 8 + c0] + gm0) * inv;
                float s11 = (acc[mt][nt][3] + rel_s[idx0 - 8 + c0 + 1] + gm1) * inv;
                acc[mt][nt][0] = s00; acc[mt][nt][1] = s01;
                acc[mt][nt][2] = s10; acc[mt][nt][3] = s11;
                rmax[mt][0] = fmaxf(rmax[mt][0], fmaxf(s00, s01));
                rmax[mt][1] = fmaxf(rmax[mt][1], fmaxf(s10, s11));
            }
        }
#pragma unroll
        for (int mt = 0; mt < 2; mt++)
#pragma unroll
            for (int hh = 0; hh < 2; hh++) {
                float v = rmax[mt][hh];
                v = fmaxf(v, __shfl_xor_sync(0xffffffff, v, 1));
                v = fmaxf(v, __shfl_xor_sync(0xffffffff, v, 2));
                rmax[mt][hh] = v;
            }
        if ((lane & 3) == 0) {
#pragma unroll
            for (int mt = 0; mt < 2; mt++)
#pragma unroll
                for (int hh = 0; hh < 2; hh++)
                    bufM[(w & 1) * 128 + wm + mt * 16 + g + hh * 8] = rmax[mt][hh];
        }
        __syncthreads();

        float fac[2][2], mnew[2][2];
#pragma unroll
        for (int mt = 0; mt < 2; mt++)
#pragma unroll
            for (int hh = 0; hh < 2; hh++) {
                int r = wm + mt * 16 + g + hh * 8;
                float tm = fmaxf(bufM[r], bufM[128 + r]);
                float mn = fmaxf(m_pr[mt][hh], tm);
                fac[mt][hh] = __expf(m_pr[mt][hh] - mn);
                mnew[mt][hh] = mn;
            }

        // ---- P = exp(S - m) -> Ps, partial sums ----
        float rsum[2][2] = {{0.f, 0.f}, {0.f, 0.f}};
#pragma unroll
        for (int mt = 0; mt < 2; mt++) {
            int rbase = wm + mt * 16 + g;
#pragma unroll
            for (int nt = 0; nt < 8; nt++) {
                int c0 = wn + nt * 8 + tg2;
                float p00 = __expf(acc[mt][nt][0] - mnew[mt][0]);
                float p01 = __expf(acc[mt][nt][1] - mnew[mt][0]);
                float p10 = __expf(acc[mt][nt][2] - mnew[mt][1]);
                float p11 = __expf(acc[mt][nt][3] - mnew[mt][1]);
                rsum[mt][0] += p00 + p01;
                rsum[mt][1] += p10 + p11;
                *(uint32_t*)&Ps[rbase * 136 + c0] = h2pack(p00, p01);
                *(uint32_t*)&Ps[(rbase + 8) * 136 + c0] = h2pack(p10, p11);
            }
        }
#pragma unroll
        for (int mt = 0; mt < 2; mt++)
#pragma unroll
            for (int hh = 0; hh < 2; hh++) {
                float v = rsum[mt][hh];
                v += __shfl_xor_sync(0xffffffff, v, 1);
                v += __shfl_xor_sync(0xffffffff, v, 2);
                rsum[mt][hh] = v;
            }
        if ((lane & 3) == 0) {
#pragma unroll
            for (int mt = 0; mt < 2; mt++)
#pragma unroll
                for (int hh = 0; hh < 2; hh++)
                    bufS[(w & 1) * 128 + wm + mt * 16 + g + hh * 8] = rsum[mt][hh];
        }
        __syncthreads();

#pragma unroll
        for (int mt = 0; mt < 2; mt++)
#pragma unroll
            for (int hh = 0; hh < 2; hh++) {
                int r = wm + mt * 16 + g + hh * 8;
                float ts = bufS[r] + bufS[128 + r];
                l_run[mt][hh] = l_run[mt][hh] * fac[mt][hh] + ts;
                m_pr[mt][hh] = mnew[mt][hh];
            }
#pragma unroll
        for (int mt = 0; mt < 2; mt++)
#pragma unroll
            for (int nt = 0; nt < 4; nt++) {
                Oacc[mt][nt][0] *= fac[mt][0]; Oacc[mt][nt][1] *= fac[mt][0];
                Oacc[mt][nt][2] *= fac[mt][1]; Oacc[mt][nt][3] *= fac[mt][1];
            }

        // ---- PV MMA ----
#pragma unroll
        for (int ks = 0; ks < 128; ks += 16) {
            uint32_t af[2][4], bf[4][2];
#pragma unroll
            for (int mt = 0; mt < 2; mt++)
                ldsm4(af[mt], smaddr(&Ps[(wm + mt * 16 + a_row) * 136 + ks + a_col]));
#pragma unroll
            for (int ntp = 0; ntp < 2; ntp++) {
                uint32_t rr[4];
                ldsm4(rr, smaddr(&Vs[(wd + ntp * 16 + b_row) * 136 + ks + b_col]));
                bf[2 * ntp][0] = rr[0]; bf[2 * ntp][1] = rr[1];
                bf[2 * ntp + 1][0] = rr[2]; bf[2 * ntp + 1][1] = rr[3];
            }
#pragma unroll
            for (int mt = 0; mt < 2; mt++)
#pragma unroll
                for (int nt = 0; nt < 4; nt++)
                    mma16(Oacc[mt][nt], af[mt], bf[nt]);
        }
        __syncthreads();
    }

    __half* Ob = g_attT + (size_t)n * L * C;
#pragma unroll
    for (int mt = 0; mt < 2; mt++) {
        float r0 = 1.0f / l_run[mt][0];
        float r1 = 1.0f / l_run[mt][1];
        int irow = i0 + wm + mt * 16 + g;
#pragma unroll
        for (int nt = 0; nt < 4; nt++) {
            int dc = h * 64 + wd + nt * 8 + tg2;
            *(uint32_t*)(Ob + (size_t)irow * C + dc) =
                h2pack(Oacc[mt][nt][0] * r0, Oacc[mt][nt][1] * r0);
            *(uint32_t*)(Ob + (size_t)(irow + 8) * C + dc) =
                h2pack(Oacc[mt][nt][2] * r1, Oacc[mt][nt][3] * r1);
        }
    }
}

// ---------------------------------------------------------------------------
// Launch
// ---------------------------------------------------------------------------
extern "C" void kernel_launch(void* const* d_in, const int* in_sizes, int n_in,
                              void* d_out, int out_size) {
    const float* x        = (const float*)d_in[0];
    const float* xorg     = (const float*)d_in[1];
    const float* abspos   = (const float*)d_in[2];
    const float* mask     = (const float*)d_in[3];
    const float* norm     = (const float*)d_in[4];
    const float* qkpos    = (const float*)d_in[5];
    const float* qkorg    = (const float*)d_in[6];
    const float* vorg     = (const float*)d_in[7];
    const float* relpos   = (const float*)d_in[8];
    const float* gate_w   = (const float*)d_in[9];
    const float* gate_b   = (const float*)d_in[10];
    const float* q_w      = (const float*)d_in[11];
    const float* k_w      = (const float*)d_in[12];
    const float* v_w      = (const float*)d_in[13];
    const float* dense_w  = (const float*)d_in[14];
    const float* dense_b  = (const float*)d_in[15];
    float* out = (float*)d_out;

    cudaFuncSetAttribute(flash_h, cudaFuncAttributeMaxDynamicSharedMemorySize, FA_B);
    cudaFuncSetAttribute(qkv_h, cudaFuncAttributeMaxDynamicSharedMemorySize, GH_B);
    cudaFuncSetAttribute(dense_h, cudaFuncAttributeMaxDynamicSharedMemorySize, GH_B);

    prep_t<<<dim3(12, 16, NB), dim3(32, 8)>>>(x, xorg, abspos, qkpos, qkorg, vorg);
    round_w_h<<<512, 256>>>(q_w, k_w, v_w, dense_w);

    gate_kernel<<<dim3(3, NB), 128>>>(x, gate_w, gate_b);

    qkv_h<<<dim3(4, 3, NB * 3), 256, GH_B>>>();

    flash_h<<<dim3(3, NB * H), 256, FA_B>>>(relpos, mask, norm);

    dense_h<<<dim3(4, 3, NB), 256, GH_B>>>(out, dense_b);
}